// round 17
// baseline (speedup 1.0000x reference)
#include <cuda_runtime.h>
#include <math.h>

#define BATCH 8
#define HH 720
#define WW 1280
#define HW (HH * WW)
#define NPIX (BATCH * HW)

#define QH (HH / 2)
#define QW (WW / 2)
#define PLANE (QH * QW)              // 230,400 entries per parity plane
#define NQUAD (BATCH * 4 * PLANE)    // 7,372,800 entries (118 MB)

#define CB 2                          // batches per chunk
#define NCHUNK (BATCH / CB)           // 4
#define CHUNK_PIX (CB * HW)           // 1,843,200 source pixels / chunk
#define CHUNK_QUAD (CB * 4 * PLANE)   // 1,843,200 quad entries / chunk

#define THREADS 256
#define SBLK (CHUNK_PIX / THREADS)        // 7200 scatter units / chunk (1 px/thr)
#define ZBLK (CHUNK_QUAD / (2 * THREADS)) // 3600 zero units / chunk (2 f4/thr)
#define NBLK (CB * PLANE / THREADS)       // 1800 norm units / chunk (2x2 blk/thr)

// Quad accumulator: entry (b, py, px, qy, qx) accumulates (cnt, ox, oy, pad)
// for the 2x2 pixel block rows {2qy+py, 2qy+py+1} x cols {2qx+px, 2qx+px+1}.
__device__ float4 g_quad[NQUAD];

__device__ __forceinline__ void red_add_v4(float4* addr, float a, float b, float c) {
    asm volatile(
        "red.global.add.v4.f32 [%0], {%1, %2, %3, %4};"
        :: "l"(addr), "f"(a), "f"(b), "f"(c), "f"(0.0f)
        : "memory");
}

// ---------------------------------------------------------------------------
// Role bodies (per-chunk). wu = role-local unit index.
// ---------------------------------------------------------------------------
__device__ __forceinline__ void do_zero(int wu, int chunk) {
    int t = wu * THREADS + threadIdx.x;              // [0, CHUNK_QUAD/2)
    float4 z = make_float4(0.f, 0.f, 0.f, 0.f);
    int base = chunk * CHUNK_QUAD;
    g_quad[base + t] = z;
    g_quad[base + t + CHUNK_QUAD / 2] = z;
}

__device__ __forceinline__ void do_scatter(int wu, int chunk,
                                           const float* __restrict__ flow,
                                           const float* __restrict__ depth) {
    int li = wu * THREADS + threadIdx.x;             // [0, CHUNK_PIX)
    int gi = chunk * CHUNK_PIX + li;

    int b = gi / HW;
    int p = gi - b * HW;
    int y = p / WW;
    int x = p - y * WW;

    const float* fbase = flow + (size_t)b * 2 * HW;
    float fx = __ldcs(fbase + p);
    float fy = __ldcs(fbase + HW + p);
    float d  = __ldcs(depth + gi);

    float x2 = (float)x + fx;
    float y2 = (float)y + fy;

    if (!(x2 >= 0.f && x2 <= (float)(WW - 1) &&
          y2 >= 0.f && y2 <= (float)(HH - 1)))
        return;

    int xL = (int)floorf(x2);
    int yT = (int)floorf(y2);

    float s = 1.f;
    if (xL == WW - 1) s *= 2.f;   // x-clamp: corners coincide
    if (yT == HH - 1) s *= 2.f;   // y-clamp: rows coincide

    float wx = -fx * d;
    float wy = -fy * d;

    int idx = ((b * 4 + (yT & 1) * 2 + (xL & 1)) * QH + (yT >> 1)) * QW + (xL >> 1);
    red_add_v4(&g_quad[idx], s * d, s * wx, s * wy);
}

__device__ __forceinline__ void do_norm(int wu, int chunk,
                                        float* __restrict__ out) {
    int t = wu * THREADS + threadIdx.x;              // [0, CB*PLANE)
    int bl = t / PLANE;                              // local batch in chunk
    int r  = t - bl * PLANE;
    int b  = chunk * CB + bl;
    int Y = r / QW;
    int X = r - Y * QW;

    const float4* pl00 = g_quad + (size_t)(b * 4 + 0) * PLANE;
    const float4* pl01 = g_quad + (size_t)(b * 4 + 1) * PLANE;
    const float4* pl10 = g_quad + (size_t)(b * 4 + 2) * PLANE;
    const float4* pl11 = g_quad + (size_t)(b * 4 + 3) * PLANE;

    float cnt[4] = {0.f, 0.f, 0.f, 0.f};
    float sox[4] = {0.f, 0.f, 0.f, 0.f};
    float soy[4] = {0.f, 0.f, 0.f, 0.f};

#define ADDP(A, pix) { cnt[pix] += (A).x; sox[pix] += (A).y; soy[pix] += (A).z; }

    int row  = Y * QW + X;
    int rowm = row - QW;

    if (Y > 0) {
        if (X > 0) { float4 a = pl11[rowm - 1]; ADDP(a, 0); }
        { float4 a = pl10[rowm]; ADDP(a, 0); ADDP(a, 1); }
        { float4 a = pl11[rowm]; ADDP(a, 1); }
    }
    if (X > 0) { float4 a = pl01[row - 1]; ADDP(a, 0); ADDP(a, 2); }
    { float4 a = pl00[row]; ADDP(a, 0); ADDP(a, 1); ADDP(a, 2); ADDP(a, 3); }
    { float4 a = pl01[row]; ADDP(a, 1); ADDP(a, 3); }
    if (X > 0) { float4 a = pl11[row - 1]; ADDP(a, 2); }
    { float4 a = pl10[row]; ADDP(a, 2); ADDP(a, 3); }
    { float4 a = pl11[row]; ADDP(a, 3); }
#undef ADDP

    float ox[4], oy[4];
#pragma unroll
    for (int k = 0; k < 4; k++) {
        ox[k] = 0.f; oy[k] = 0.f;
        if (cnt[k] > 0.f) {
            float inv = 1.f / cnt[k];
            ox[k] = sox[k] * inv;
            oy[k] = soy[k] * inv;
        }
    }

    int y0 = 2 * Y, x0 = 2 * X;
    float* obase = out + (size_t)b * 2 * HW;
    float* orow0 = obase + y0 * WW + x0;
    float* orow1 = orow0 + WW;

    __stcs(reinterpret_cast<float2*>(orow0),      make_float2(ox[0], ox[1]));
    __stcs(reinterpret_cast<float2*>(orow1),      make_float2(ox[2], ox[3]));
    __stcs(reinterpret_cast<float2*>(orow0 + HW), make_float2(oy[0], oy[1]));
    __stcs(reinterpret_cast<float2*>(orow1 + HW), make_float2(oy[2], oy[3]));
}

// ---------------------------------------------------------------------------
// Striped fused kernels. Unit ratio S:Z:N = 7200:3600:1800 = 4:2:1.
// mode 0: Z only.              mode 1: S+Z (stripe 3: 2S,1Z).
// mode 2: S+Z+N (stripe 7: 4S,2Z,1N).  mode 3: S+N (stripe 5: 4S,1N).
// mode 4: N only.
// ---------------------------------------------------------------------------
__global__ void pipe_kernel(const float* __restrict__ flow,
                            const float* __restrict__ depth,
                            float* __restrict__ out,
                            int mode, int cS, int cZ, int cN) {
    int blk = blockIdx.x;
    if (mode == 0) {
        do_zero(blk, cZ);
    } else if (mode == 1) {
        int g = blk / 3, r = blk - g * 3;
        if (r < 2) do_scatter(g * 2 + r, cS, flow, depth);
        else       do_zero(g, cZ);
    } else if (mode == 2) {
        int g = blk / 7, r = blk - g * 7;
        if (r < 4)      do_scatter(g * 4 + r, cS, flow, depth);
        else if (r < 6) do_zero(g * 2 + (r - 4), cZ);
        else            do_norm(g, cN, out);
    } else if (mode == 3) {
        int g = blk / 5, r = blk - g * 5;
        if (r < 4) do_scatter(g * 4 + r, cS, flow, depth);
        else       do_norm(g, cN, out);
    } else {
        do_norm(blk, cN, out);
    }
}

extern "C" void kernel_launch(void* const* d_in, const int* in_sizes, int n_in,
                              void* d_out, int out_size) {
    const float* flow  = (const float*)d_in[0];   // (B, 2, H, W)
    const float* depth = (const float*)d_in[1];   // (B, 1, H, W)
    float* out = (float*)d_out;                   // (B, 2, H, W)

    (void)in_sizes; (void)n_in; (void)out_size;

    // Pipeline: Z0 | S0+Z1 | S1+Z2+N0 | S2+Z3+N1 | S3+N2 | N3
    pipe_kernel<<<ZBLK, THREADS>>>(flow, depth, out, 0, 0, 0, 0);
    pipe_kernel<<<SBLK + ZBLK, THREADS>>>(flow, depth, out, 1, 0, 1, 0);
    pipe_kernel<<<SBLK + ZBLK + NBLK, THREADS>>>(flow, depth, out, 2, 1, 2, 0);
    pipe_kernel<<<SBLK + ZBLK + NBLK, THREADS>>>(flow, depth, out, 2, 2, 3, 1);
    pipe_kernel<<<SBLK + NBLK, THREADS>>>(flow, depth, out, 3, 3, 0, 2);
    pipe_kernel<<<NBLK, THREADS>>>(flow, depth, out, 4, 0, 0, 3);
}